// round 1
// baseline (speedup 1.0000x reference)
#include <cuda_runtime.h>
#include <math_constants.h>

#define D    768
#define Nn   100000
#define NC   64
#define Bx   8192
#define KK   50
#define CCLS 10

// ---------------- scratch (device globals; no allocation allowed) ----------
__device__ float g_gram[NC * NC];
__device__ float g_inv [NC * NC];
__device__ float g_WC  [CCLS * NC];
__device__ float g_M1  [CCLS * NC];
__device__ float g_Wp  [CCLS * D];
__device__ float g_score[NC * Nn];   // 25.6 MB scratch for ranking scores
__device__ int   g_idx [NC * KK];
__device__ float g_dot [NC];

// ---------------- gram = C^T C  (64 blocks x 64 threads) -------------------
__global__ void gram_kernel(const float* __restrict__ C) {
    __shared__ float ci[D];
    int i = blockIdx.x;
    for (int d = threadIdx.x; d < D; d += 64) ci[d] = C[d * NC + i];
    __syncthreads();
    int j = threadIdx.x;
    float acc = 0.f;
    for (int d = 0; d < D; d++) acc += ci[d] * C[d * NC + j];
    g_gram[i * NC + j] = acc;
}

// ---------------- gram statistics (3 scalars) -------------------------------
__global__ void gramstats_kernel(float* __restrict__ out) {
    __shared__ float s1[256], s2[256], s3[256];
    int tid = threadIdx.x;
    float off = 0.f, dia = 0.f, ad = 0.f;
    for (int idx = tid; idx < NC * NC; idx += 256) {
        int i = idx >> 6, j = idx & 63;
        float g = g_gram[idx];
        float e = (i == j) ? 1.f : 0.f;
        if (i == j) dia += g; else off += g;
        ad += fabsf(g - e);
    }
    s1[tid] = off; s2[tid] = dia; s3[tid] = ad;
    __syncthreads();
    for (int s = 128; s; s >>= 1) {
        if (tid < s) { s1[tid] += s1[tid + s]; s2[tid] += s2[tid + s]; s3[tid] += s3[tid + s]; }
        __syncthreads();
    }
    if (tid == 0) {
        out[163841] = s1[0] / 4096.f;   // L_sparse_2 = mean offdiag
        out[163842] = s2[0] / 4096.f;   // norm_metrics = mean diag
        out[163843] = s3[0] / 4096.f;   // similarity_penalty
    }
}

// ---------------- Gauss-Jordan inverse of gram (SPD, 64x64) ----------------
__global__ void inv_kernel() {
    __shared__ float aug[NC][2 * NC];
    __shared__ float f[NC];
    __shared__ float pinv;
    int tid = threadIdx.x;  // 256
    for (int idx = tid; idx < NC * 2 * NC; idx += 256) {
        int i = idx >> 7, j = idx & 127;
        aug[i][j] = (j < NC) ? g_gram[i * NC + j] : ((j - NC == i) ? 1.f : 0.f);
    }
    __syncthreads();
    for (int k = 0; k < NC; k++) {
        if (tid == 0) pinv = 1.f / aug[k][k];
        __syncthreads();
        if (tid < 128) aug[k][tid] *= pinv;
        __syncthreads();
        if (tid < NC) f[tid] = (tid == k) ? 0.f : aug[tid][k];
        __syncthreads();
        for (int idx = tid; idx < NC * 2 * NC; idx += 256) {
            int i = idx >> 7, j = idx & 127;
            if (i != k) aug[i][j] -= f[i] * aug[k][j];
        }
        __syncthreads();
    }
    for (int idx = tid; idx < NC * NC; idx += 256) {
        int i = idx >> 6, j = idx & 63;
        g_inv[idx] = aug[i][NC + j];
    }
}

// ---------------- WC = W @ C  (10x64) ---------------------------------------
__global__ void wc_kernel(const float* __restrict__ W, const float* __restrict__ C) {
    int i = blockIdx.x, c = threadIdx.x;
    float acc = 0.f;
    for (int d = 0; d < D; d++) acc += W[i * D + d] * C[d * NC + c];
    g_WC[i * NC + c] = acc;
}

// ---------------- M1 = WC @ inv ---------------------------------------------
__global__ void m1_kernel() {
    int i = blockIdx.x, c = threadIdx.x;
    float acc = 0.f;
    for (int q = 0; q < NC; q++) acc += g_WC[i * NC + q] * g_inv[q * NC + c];
    g_M1[i * NC + c] = acc;
}

// ---------------- Wp = M1 @ C^T  (10x768) -----------------------------------
__global__ void wp_kernel(const float* __restrict__ C) {
    int gid = blockIdx.x * 256 + threadIdx.x;
    int i = gid / D, dd = gid % D;
    float acc = 0.f;
    for (int c = 0; c < NC; c++) acc += g_M1[i * NC + c] * C[dd * NC + c];
    g_Wp[i * D + dd] = acc;
}

// ---------------- score[c][n] = (C^T T)[c][n] - 0.5*||t_n||^2 ---------------
// 64 rows x 128-column tiles; 256 threads; each thread owns 8x4 outputs.
#define BN 128
#define DK 48
__global__ void __launch_bounds__(256) score_kernel(const float* __restrict__ C,
                                                    const float* __restrict__ T) {
    __shared__ __align__(16) float Cs[DK][NC];
    __shared__ __align__(16) float Ts[DK][BN];
    __shared__ float4 snorm[32];
    int tid = threadIdx.x;
    int tx = tid & 31, ty = tid >> 5;
    int n0 = blockIdx.x * BN;
    float acc[8][4];
#pragma unroll
    for (int i = 0; i < 8; i++)
#pragma unroll
        for (int j = 0; j < 4; j++) acc[i][j] = 0.f;
    float4 nrm = make_float4(0.f, 0.f, 0.f, 0.f);

    for (int d0 = 0; d0 < D; d0 += DK) {
        __syncthreads();
        for (int idx = tid; idx < DK * NC; idx += 256) {
            int dd = idx >> 6, c = idx & 63;
            Cs[dd][c] = C[(d0 + dd) * NC + c];
        }
        for (int idx = tid; idx < DK * BN; idx += 256) {
            int dd = idx >> 7, nn = idx & 127;
            int n = n0 + nn;
            Ts[dd][nn] = (n < Nn) ? T[(d0 + dd) * Nn + n] : 0.f;
        }
        __syncthreads();
#pragma unroll 4
        for (int dd = 0; dd < DK; dd++) {
            float4 tv  = *reinterpret_cast<const float4*>(&Ts[dd][tx * 4]);
            float4 cv0 = *reinterpret_cast<const float4*>(&Cs[dd][ty * 8]);
            float4 cv1 = *reinterpret_cast<const float4*>(&Cs[dd][ty * 8 + 4]);
            float cvv[8] = {cv0.x, cv0.y, cv0.z, cv0.w, cv1.x, cv1.y, cv1.z, cv1.w};
#pragma unroll
            for (int i = 0; i < 8; i++) {
                acc[i][0] += cvv[i] * tv.x;
                acc[i][1] += cvv[i] * tv.y;
                acc[i][2] += cvv[i] * tv.z;
                acc[i][3] += cvv[i] * tv.w;
            }
            if (ty == 0) {
                nrm.x += tv.x * tv.x; nrm.y += tv.y * tv.y;
                nrm.z += tv.z * tv.z; nrm.w += tv.w * tv.w;
            }
        }
    }
    if (ty == 0) snorm[tx] = nrm;
    __syncthreads();
    float4 nr = snorm[tx];
    float nb[4] = {nr.x, nr.y, nr.z, nr.w};
    int nbase = n0 + tx * 4;
#pragma unroll
    for (int i = 0; i < 8; i++) {
        int c = ty * 8 + i;
        if (nbase + 3 < Nn) {
            float4 o;
            o.x = acc[i][0] - 0.5f * nb[0];
            o.y = acc[i][1] - 0.5f * nb[1];
            o.z = acc[i][2] - 0.5f * nb[2];
            o.w = acc[i][3] - 0.5f * nb[3];
            *reinterpret_cast<float4*>(&g_score[c * Nn + nbase]) = o;
        } else {
#pragma unroll
            for (int j = 0; j < 4; j++)
                if (nbase + j < Nn) g_score[c * Nn + nbase + j] = acc[i][j] - 0.5f * nb[j];
        }
    }
}

// ---------------- top-50 per concept row (argmax of score) ------------------
#define LT 16
__global__ void __launch_bounds__(256) topk_kernel() {
    __shared__ float sv[256 * LT];
    __shared__ int   si[256 * LT];
    __shared__ float rv[256];
    __shared__ int   rp[256];
    int c = blockIdx.x, tid = threadIdx.x;
    float lv[LT]; int li[LT];
#pragma unroll
    for (int q = 0; q < LT; q++) { lv[q] = -CUDART_INF_F; li[q] = 0; }
    const float* row = &g_score[c * Nn];
    for (int n = tid; n < Nn; n += 256) {
        float s = row[n];
        if (s > lv[0]) {
            int pos = 0;
#pragma unroll
            for (int q = 1; q < LT; q++) {
                if (s > lv[q]) { lv[q - 1] = lv[q]; li[q - 1] = li[q]; pos = q; }
            }
            lv[pos] = s; li[pos] = n;
        }
    }
#pragma unroll
    for (int q = 0; q < LT; q++) { sv[tid * LT + q] = lv[q]; si[tid * LT + q] = li[q]; }
    __syncthreads();
    for (int it = 0; it < KK; it++) {
        float best = -CUDART_INF_F; int bp = 0;
#pragma unroll
        for (int q = 0; q < LT; q++) {
            float v = sv[tid * LT + q];
            if (v > best) { best = v; bp = tid * LT + q; }
        }
        rv[tid] = best; rp[tid] = bp;
        __syncthreads();
        for (int s = 128; s; s >>= 1) {
            if (tid < s && rv[tid + s] > rv[tid]) { rv[tid] = rv[tid + s]; rp[tid] = rp[tid + s]; }
            __syncthreads();
        }
        if (tid == 0) { g_idx[c * KK + it] = si[rp[0]]; sv[rp[0]] = -CUDART_INF_F; }
        __syncthreads();
    }
}

// ---------------- per-concept knn dot sum ------------------------------------
__global__ void __launch_bounds__(256) dot_kernel(const float* __restrict__ C,
                                                  const float* __restrict__ T) {
    __shared__ float cs[D];
    __shared__ int   sid[KK];
    __shared__ float red[256];
    int c = blockIdx.x, tid = threadIdx.x;
    for (int d = tid; d < D; d += 256) cs[d] = C[d * NC + c];
    if (tid < KK) sid[tid] = g_idx[c * KK + tid];
    __syncthreads();
    float acc = 0.f;
    for (int kk = 0; kk < KK; kk++) {
        int n = sid[kk];
        for (int d = tid; d < D; d += 256) acc += cs[d] * T[d * Nn + n];
    }
    red[tid] = acc;
    __syncthreads();
    for (int s = 128; s; s >>= 1) {
        if (tid < s) red[tid] += red[tid + s];
        __syncthreads();
    }
    if (tid == 0) g_dot[c] = red[0];
}

__global__ void finalize_kernel(float* __restrict__ out) {
    __shared__ float s[64];
    s[threadIdx.x] = g_dot[threadIdx.x];
    __syncthreads();
    for (int st = 32; st; st >>= 1) {
        if (threadIdx.x < st) s[threadIdx.x] += s[threadIdx.x + st];
        __syncthreads();
    }
    if (threadIdx.x == 0) out[163840] = s[0] / (float)(NC * KK);   // L_sparse_1
}

// ---------------- predictions: [orig_pred | y_pred] = x @ [W | Wp]^T + b ----
#define PR  64
#define PDK 128
__global__ void __launch_bounds__(256) pred_kernel(const float* __restrict__ X,
                                                   const float* __restrict__ W,
                                                   const float* __restrict__ b,
                                                   float* __restrict__ out) {
    __shared__ float xs[PR][PDK + 1];
    __shared__ float ws[2 * CCLS][PDK + 1];
    int tid = threadIdx.x;
    int g = tid & 3;        // class group 0..3 (5 classes each)
    int r = tid >> 2;       // local row 0..63
    int r0 = blockIdx.x * PR;
    float acc[5];
#pragma unroll
    for (int q = 0; q < 5; q++) acc[q] = 0.f;

    for (int d0 = 0; d0 < D; d0 += PDK) {
        __syncthreads();
        for (int idx = tid; idx < PR * PDK; idx += 256) {
            int rr = idx >> 7, dd = idx & 127;
            xs[rr][dd] = X[(r0 + rr) * D + d0 + dd];
        }
        for (int idx = tid; idx < 2 * CCLS * PDK; idx += 256) {
            int cr = idx >> 7, dd = idx & 127;
            ws[cr][dd] = (cr < CCLS) ? W[cr * D + d0 + dd] : g_Wp[(cr - CCLS) * D + d0 + dd];
        }
        __syncthreads();
        for (int dd = 0; dd < PDK; dd++) {
            float xv = xs[r][dd];
#pragma unroll
            for (int q = 0; q < 5; q++) acc[q] += xv * ws[g * 5 + q][dd];
        }
    }
#pragma unroll
    for (int q = 0; q < 5; q++) {
        int cls = g * 5 + q;
        int gr = r0 + r;
        float v = acc[q] + b[(cls < CCLS) ? cls : cls - CCLS];
        if (cls < CCLS) out[gr * CCLS + cls] = v;
        else            out[Bx * CCLS + gr * CCLS + (cls - CCLS)] = v;
    }
}

// ---------------- launcher ---------------------------------------------------
extern "C" void kernel_launch(void* const* d_in, const int* in_sizes, int n_in,
                              void* d_out, int out_size) {
    const float* X = (const float*)d_in[0];   // train_embedding [8192,768]
    // d_in[1] = h_x (unused by the reference outputs)
    const float* C = (const float*)d_in[2];   // concept [768,64]
    const float* T = (const float*)d_in[3];   // train_embeddings_T [768,100000]
    const float* W = (const float*)d_in[4];   // W [10,768]
    const float* b = (const float*)d_in[5];   // b [10]
    float* out = (float*)d_out;

    gram_kernel<<<64, 64>>>(C);
    gramstats_kernel<<<1, 256>>>(out);
    inv_kernel<<<1, 256>>>();
    wc_kernel<<<CCLS, NC>>>(W, C);
    m1_kernel<<<CCLS, NC>>>();
    wp_kernel<<<30, 256>>>(C);
    score_kernel<<<(Nn + BN - 1) / BN, 256>>>(C, T);
    topk_kernel<<<NC, 256>>>();
    dot_kernel<<<NC, 256>>>(C, T);
    finalize_kernel<<<1, 64>>>(out);
    pred_kernel<<<Bx / PR, 256>>>(X, W, b, out);
}

// round 3
// speedup vs baseline: 3.3532x; 3.3532x over previous
#include <cuda_runtime.h>
#include <math_constants.h>

#define D    768
#define Nn   100000
#define NC   64
#define Bx   8192
#define KK   50
#define CCLS 10

// ---------------- scratch (device globals; no allocation allowed) ----------
__device__ float g_gram[NC * NC];
__device__ float g_WC  [CCLS * NC];    // WC[i][c] = (W @ C)[i][c]
__device__ float g_Z   [NC * CCLS];   // Z = G^-1 (WC)^T
__device__ float g_Wp  [CCLS * D];
__device__ float g_score[NC * Nn];    // score[c][n] = c.t - 0.5||t||^2 (tf32 mma)
__device__ float g_halfnorm[Nn];      // 0.5 ||t_n||^2
__device__ float g_cv  [NC * 8 * KK]; // stage-1 candidate values
__device__ int   g_ci  [NC * 8 * KK]; // stage-1 candidate indices
__device__ float g_dot [NC];

// ---------------- stream fork (created at static-init, before checkpoints) --
struct StreamInit {
    cudaStream_t s2;
    cudaEvent_t  evF, evJ;
    StreamInit() {
        cudaStreamCreateWithFlags(&s2, cudaStreamNonBlocking);
        cudaEventCreateWithFlags(&evF, cudaEventDisableTiming);
        cudaEventCreateWithFlags(&evJ, cudaEventDisableTiming);
    }
};
static StreamInit g_si;

// ---------------- helpers ----------------------------------------------------
__device__ __forceinline__ unsigned f2tf32(float f) {
    unsigned u;
    asm("cvt.rna.tf32.f32 %0, %1;" : "=r"(u) : "f"(f));
    return u;
}

__device__ __forceinline__ void mma_tf32(float c[4], unsigned a0, unsigned a1,
                                         unsigned a2, unsigned a3,
                                         unsigned b0, unsigned b1) {
    asm volatile(
        "mma.sync.aligned.m16n8k8.row.col.f32.tf32.tf32.f32 "
        "{%0,%1,%2,%3}, {%4,%5,%6,%7}, {%8,%9}, {%0,%1,%2,%3};\n"
        : "+f"(c[0]), "+f"(c[1]), "+f"(c[2]), "+f"(c[3])
        : "r"(a0), "r"(a1), "r"(a2), "r"(a3), "r"(b0), "r"(b1));
}

__device__ __forceinline__ unsigned long long packkey(float v, int n) {
    unsigned u = __float_as_uint(v);
    u = (u & 0x80000000u) ? ~u : (u | 0x80000000u);
    return ((unsigned long long)u << 32) | (unsigned)n;
}

// ================= score GEMM: S = C^T T - 0.5||t||^2 (tf32 mma) ============
// Block: 256 threads (8 warps), tile 64(c) x 256(n), K chunks of 32.
// Warp w: m-tile = (w&3)*16, n-half = (w>>2)*128 (16 n-subtiles of 8).
#define TS_LD 264   // 264 % 32 == 8 -> conflict-free B-frag lds
#define CS_LD 72    // 72 % 32 == 8  -> conflict-free A-frag lds
__global__ void __launch_bounds__(256) score_mma_kernel(const float* __restrict__ C,
                                                        const float* __restrict__ T) {
    __shared__ unsigned TsU[32 * TS_LD];   // 33792 B
    __shared__ unsigned CsU[32 * CS_LD];   //  9216 B
    __shared__ float    hnrm[256];         //  1024 B
    __shared__ float4   snrm[4][64];       //  4096 B

    int tid  = threadIdx.x;
    int lane = tid & 31, w = tid >> 5;
    int tig  = lane & 3, gid = lane >> 2;
    int m0   = (w & 3) * 16;
    int nn0  = (w >> 2) * 128;
    int n0   = blockIdx.x * 256;

    int col4 = tid & 63;          // T-loader column group (4 floats)
    int rb   = tid >> 6;          // T-loader row base
    bool colok = (n0 + 4 * col4) < Nn;

    float acc[16][4];
#pragma unroll
    for (int j = 0; j < 16; j++)
#pragma unroll
        for (int q = 0; q < 4; q++) acc[j][q] = 0.f;
    float4 nrm = make_float4(0.f, 0.f, 0.f, 0.f);

    for (int ch = 0; ch < D / 32; ch++) {
        int d0 = ch * 32;
        __syncthreads();
        // C tile: 32 x 64 -> CsU[k][c]
#pragma unroll
        for (int ii = 0; ii < 8; ii++) {
            int idx = tid + 256 * ii;
            int row = idx >> 6, col = idx & 63;
            CsU[row * CS_LD + col] = f2tf32(C[(d0 + row) * NC + col]);
        }
        // T tile: 32 x 256 -> TsU[k][n], norms accumulated pre-conversion
#pragma unroll
        for (int ii = 0; ii < 8; ii++) {
            int r = rb + 4 * ii;
            float4 v = make_float4(0.f, 0.f, 0.f, 0.f);
            if (colok)
                v = *reinterpret_cast<const float4*>(T + (size_t)(d0 + r) * Nn + n0 + 4 * col4);
            nrm.x += v.x * v.x; nrm.y += v.y * v.y;
            nrm.z += v.z * v.z; nrm.w += v.w * v.w;
            uint4 u;
            u.x = f2tf32(v.x); u.y = f2tf32(v.y);
            u.z = f2tf32(v.z); u.w = f2tf32(v.w);
            *reinterpret_cast<uint4*>(&TsU[r * TS_LD + 4 * col4]) = u;
        }
        __syncthreads();
        // compute: 4 k-steps of 8
#pragma unroll
        for (int s = 0; s < 4; s++) {
            int k0 = s * 8;
            unsigned a0 = CsU[(k0 + tig) * CS_LD + m0 + gid];
            unsigned a1 = CsU[(k0 + tig) * CS_LD + m0 + gid + 8];
            unsigned a2 = CsU[(k0 + tig + 4) * CS_LD + m0 + gid];
            unsigned a3 = CsU[(k0 + tig + 4) * CS_LD + m0 + gid + 8];
#pragma unroll
            for (int j = 0; j < 16; j++) {
                unsigned b0 = TsU[(k0 + tig) * TS_LD + nn0 + 8 * j + gid];
                unsigned b1 = TsU[(k0 + tig + 4) * TS_LD + nn0 + 8 * j + gid];
                mma_tf32(acc[j], a0, a1, a2, a3, b0, b1);
            }
        }
    }

    // combine norms: 4 partials per column group
    __syncthreads();
    snrm[rb][col4] = nrm;
    __syncthreads();
    if (tid < 64) {
        float4 a = snrm[0][tid], b = snrm[1][tid], c2 = snrm[2][tid], d = snrm[3][tid];
        hnrm[4 * tid + 0] = 0.5f * (a.x + b.x + c2.x + d.x);
        hnrm[4 * tid + 1] = 0.5f * (a.y + b.y + c2.y + d.y);
        hnrm[4 * tid + 2] = 0.5f * (a.z + b.z + c2.z + d.z);
        hnrm[4 * tid + 3] = 0.5f * (a.w + b.w + c2.w + d.w);
    }
    __syncthreads();
    if (n0 + tid < Nn) g_halfnorm[n0 + tid] = hnrm[tid];

    // epilogue: write scores
#pragma unroll
    for (int j = 0; j < 16; j++) {
        int ncol = nn0 + 8 * j + 2 * tig;
        int n = n0 + ncol;
        int r0 = m0 + gid, r1 = r0 + 8;
        if (n < Nn) {
            float h = hnrm[ncol];
            g_score[(size_t)r0 * Nn + n] = acc[j][0] - h;
            g_score[(size_t)r1 * Nn + n] = acc[j][2] - h;
        }
        if (n + 1 < Nn) {
            float h = hnrm[ncol + 1];
            g_score[(size_t)r0 * Nn + n + 1] = acc[j][1] - h;
            g_score[(size_t)r1 * Nn + n + 1] = acc[j][3] - h;
        }
    }
}

// ================= topk stage 1: per (concept, segment) top-50 ==============
#define LT 10
__global__ void __launch_bounds__(256) topk1_kernel() {
    int c = blockIdx.y, seg = blockIdx.x, tid = threadIdx.x;
    const int SEG = Nn / 8;
    int nbeg = seg * SEG, nend = nbeg + SEG;

    float lv[LT]; int li[LT];
#pragma unroll
    for (int q = 0; q < LT; q++) { lv[q] = -CUDART_INF_F; li[q] = 0; }
    const float* row = g_score + (size_t)c * Nn;
    for (int n = nbeg + tid; n < nend; n += 256) {
        float s = row[n];
        if (s > lv[0]) {
            int pos = 0;
#pragma unroll
            for (int q = 1; q < LT; q++)
                if (s > lv[q]) { lv[q - 1] = lv[q]; li[q - 1] = li[q]; pos = q; }
            lv[pos] = s; li[pos] = n;
        }
    }

    __shared__ unsigned long long wmax[8];
    __shared__ unsigned long long winner;
    int p = LT - 1;
    unsigned long long cur = packkey(lv[p], li[p]);
    int obase = (c * 8 + seg) * KK;
    for (int it = 0; it < KK; it++) {
        unsigned long long m = cur;
#pragma unroll
        for (int o = 16; o; o >>= 1) {
            unsigned long long t = __shfl_down_sync(0xffffffffu, m, o);
            if (t > m) m = t;
        }
        if ((tid & 31) == 0) wmax[tid >> 5] = m;
        __syncthreads();
        if (tid == 0) {
            unsigned long long b = wmax[0];
#pragma unroll
            for (int q = 1; q < 8; q++) if (wmax[q] > b) b = wmax[q];
            winner = b;
        }
        __syncthreads();
        if (cur == winner) {
            g_cv[obase + it] = lv[p];
            g_ci[obase + it] = li[p];
            p--;
            cur = (p >= 0) ? packkey(lv[p], li[p]) : 0ull;
        }
    }
}

// ================= topk stage 2: merge 400 -> 50, sum (score+halfnorm) ======
__global__ void __launch_bounds__(256) topk2_kernel() {
    int c = blockIdx.x, tid = threadIdx.x;
    int base = c * 8 * KK;   // 400 candidates
    float lv[2]; int li[2];
    lv[0] = g_cv[base + tid];          li[0] = g_ci[base + tid];
    if (tid + 256 < 8 * KK) { lv[1] = g_cv[base + tid + 256]; li[1] = g_ci[base + tid + 256]; }
    else                    { lv[1] = -CUDART_INF_F;          li[1] = 0; }
    if (lv[0] > lv[1]) { float tv = lv[0]; lv[0] = lv[1]; lv[1] = tv;
                         int   ti = li[0]; li[0] = li[1]; li[1] = ti; }

    __shared__ unsigned long long wmax[8];
    __shared__ unsigned long long winner;
    __shared__ float selv[KK];
    __shared__ int   seli[KK];
    __shared__ float red[64];

    int p = 1;
    unsigned long long cur = packkey(lv[p], li[p]);
    for (int it = 0; it < KK; it++) {
        unsigned long long m = cur;
#pragma unroll
        for (int o = 16; o; o >>= 1) {
            unsigned long long t = __shfl_down_sync(0xffffffffu, m, o);
            if (t > m) m = t;
        }
        if ((tid & 31) == 0) wmax[tid >> 5] = m;
        __syncthreads();
        if (tid == 0) {
            unsigned long long b = wmax[0];
#pragma unroll
            for (int q = 1; q < 8; q++) if (wmax[q] > b) b = wmax[q];
            winner = b;
        }
        __syncthreads();
        if (cur == winner) {
            selv[it] = lv[p]; seli[it] = li[p];
            p--;
            cur = (p >= 0) ? packkey(lv[p], li[p]) : 0ull;
        }
    }
    __syncthreads();
    if (tid < 64) red[tid] = (tid < KK) ? (selv[tid] + g_halfnorm[seli[tid]]) : 0.f;
    __syncthreads();
    if (tid < 32) { red[tid] += red[tid + 32]; }
    __syncthreads();
    if (tid < 16) red[tid] += red[tid + 16];
    __syncthreads();
    if (tid < 8) red[tid] += red[tid + 8];
    __syncthreads();
    if (tid < 4) red[tid] += red[tid + 4];
    __syncthreads();
    if (tid == 0) g_dot[c] = red[0] + red[1] + red[2] + red[3];
}

__global__ void finalize_kernel(float* __restrict__ out) {
    __shared__ float s[64];
    s[threadIdx.x] = g_dot[threadIdx.x];
    __syncthreads();
    for (int st = 32; st; st >>= 1) {
        if (threadIdx.x < st) s[threadIdx.x] += s[threadIdx.x + st];
        __syncthreads();
    }
    if (threadIdx.x == 0) out[163840] = s[0] / (float)(NC * KK);   // L_sparse_1
}

// ================= prologue branch ===========================================
__global__ void __launch_bounds__(256) gram2_kernel(const float* __restrict__ C) {
    __shared__ float ci[D];
    __shared__ float part[4][NC];
    int i = blockIdx.x, t = threadIdx.x;
    for (int d = t; d < D; d += 256) ci[d] = C[d * NC + i];
    __syncthreads();
    int j = t & 63, q = t >> 6;
    float acc = 0.f;
    int d0 = q * (D / 4);
    for (int d = d0; d < d0 + D / 4; d++) acc += ci[d] * C[d * NC + j];
    part[q][j] = acc;
    __syncthreads();
    if (t < NC) g_gram[i * NC + t] = part[0][t] + part[1][t] + part[2][t] + part[3][t];
}

__global__ void gramstats_kernel(float* __restrict__ out) {
    __shared__ float s1[256], s2[256], s3[256];
    int tid = threadIdx.x;
    float off = 0.f, dia = 0.f, ad = 0.f;
    for (int idx = tid; idx < NC * NC; idx += 256) {
        int i = idx >> 6, j = idx & 63;
        float g = g_gram[idx];
        float e = (i == j) ? 1.f : 0.f;
        if (i == j) dia += g; else off += g;
        ad += fabsf(g - e);
    }
    s1[tid] = off; s2[tid] = dia; s3[tid] = ad;
    __syncthreads();
    for (int s = 128; s; s >>= 1) {
        if (tid < s) { s1[tid] += s1[tid + s]; s2[tid] += s2[tid + s]; s3[tid] += s3[tid + s]; }
        __syncthreads();
    }
    if (tid == 0) {
        out[163841] = s1[0] / 4096.f;   // L_sparse_2
        out[163842] = s2[0] / 4096.f;   // norm_metrics
        out[163843] = s3[0] / 4096.f;   // similarity_penalty
    }
}

__global__ void __launch_bounds__(256) wc2_kernel(const float* __restrict__ W,
                                                  const float* __restrict__ C) {
    __shared__ float wi[D];
    __shared__ float part[4][NC];
    int i = blockIdx.x, t = threadIdx.x;
    for (int d = t; d < D; d += 256) wi[d] = W[i * D + d];
    __syncthreads();
    int c = t & 63, q = t >> 6;
    float acc = 0.f;
    int d0 = q * (D / 4);
    for (int d = d0; d < d0 + D / 4; d++) acc += wi[d] * C[d * NC + c];
    part[q][c] = acc;
    __syncthreads();
    if (t < NC) g_WC[i * NC + t] = part[0][t] + part[1][t] + part[2][t] + part[3][t];
}

// Gauss-Jordan solve G Z = (WC)^T  (SPD, no pivoting), 64x(64+10) augmented
// 192 threads: lanes [0,74) scale the pivot row, lanes [128,192) write all
// 64 elimination factors (fixes the R2 bug where f[54..63] was never set).
__global__ void __launch_bounds__(192) solve_kernel() {
    __shared__ float aug[NC][80];
    __shared__ float f[NC];
    __shared__ float pinv;
    int t = threadIdx.x;   // 192
    for (int idx = t; idx < NC * 74; idx += 192) {
        int i = idx / 74, j = idx % 74;
        aug[i][j] = (j < NC) ? g_gram[i * NC + j] : g_WC[(j - NC) * NC + i];
    }
    __syncthreads();
    for (int k = 0; k < NC; k++) {
        if (t == 0) pinv = 1.f / aug[k][k];
        __syncthreads();
        if (t < 74) aug[k][t] *= pinv;
        if (t >= 128) {
            int i = t - 128;   // 0..63
            f[i] = (i == k) ? 0.f : aug[i][k];
        }
        __syncthreads();
        for (int idx = t; idx < NC * 74; idx += 192) {
            int i = idx / 74, j = idx % 74;
            if (i != k) aug[i][j] -= f[i] * aug[k][j];
        }
        __syncthreads();
    }
    for (int idx = t; idx < NC * CCLS; idx += 192) {
        int cc = idx / CCLS, i = idx % CCLS;
        g_Z[cc * CCLS + i] = aug[cc][NC + i];
    }
}

__global__ void __launch_bounds__(256) wp2_kernel(const float* __restrict__ C) {
    __shared__ float z[NC * CCLS];
    int t = threadIdx.x;
    for (int idx = t; idx < NC * CCLS; idx += 256) z[idx] = g_Z[idx];
    __syncthreads();
    int gid = blockIdx.x * 256 + t;   // 7680 total
    int i = gid / D, d = gid % D;
    float acc = 0.f;
    for (int c = 0; c < NC; c++) acc += C[d * NC + c] * z[c * CCLS + i];
    g_Wp[i * D + d] = acc;
}

// ---------------- predictions: [orig_pred | y_pred] = x @ [W | Wp]^T + b ----
#define PR  64
#define PDK 128
__global__ void __launch_bounds__(256) pred_kernel(const float* __restrict__ X,
                                                   const float* __restrict__ W,
                                                   const float* __restrict__ b,
                                                   float* __restrict__ out) {
    __shared__ float xs[PR][PDK + 1];
    __shared__ float ws[2 * CCLS][PDK + 1];
    int tid = threadIdx.x;
    int g = tid & 3;
    int r = tid >> 2;
    int r0 = blockIdx.x * PR;
    float acc[5];
#pragma unroll
    for (int q = 0; q < 5; q++) acc[q] = 0.f;

    for (int d0 = 0; d0 < D; d0 += PDK) {
        __syncthreads();
        for (int idx = tid; idx < PR * PDK; idx += 256) {
            int rr = idx >> 7, dd = idx & 127;
            xs[rr][dd] = X[(r0 + rr) * D + d0 + dd];
        }
        for (int idx = tid; idx < 2 * CCLS * PDK; idx += 256) {
            int cr = idx >> 7, dd = idx & 127;
            ws[cr][dd] = (cr < CCLS) ? W[cr * D + d0 + dd] : g_Wp[(cr - CCLS) * D + d0 + dd];
        }
        __syncthreads();
        for (int dd = 0; dd < PDK; dd++) {
            float xv = xs[r][dd];
#pragma unroll
            for (int q = 0; q < 5; q++) acc[q] += xv * ws[g * 5 + q][dd];
        }
    }
#pragma unroll
    for (int q = 0; q < 5; q++) {
        int cls = g * 5 + q;
        int gr = r0 + r;
        float v = acc[q] + b[(cls < CCLS) ? cls : cls - CCLS];
        if (cls < CCLS) out[gr * CCLS + cls] = v;
        else            out[Bx * CCLS + gr * CCLS + (cls - CCLS)] = v;
    }
}

// ---------------- launcher ---------------------------------------------------
extern "C" void kernel_launch(void* const* d_in, const int* in_sizes, int n_in,
                              void* d_out, int out_size) {
    const float* X = (const float*)d_in[0];   // train_embedding [8192,768]
    const float* C = (const float*)d_in[2];   // concept [768,64]
    const float* T = (const float*)d_in[3];   // train_embeddings_T [768,100000]
    const float* W = (const float*)d_in[4];   // W [10,768]
    const float* b = (const float*)d_in[5];   // b [10]
    float* out = (float*)d_out;

    // fork prologue branch onto s2
    cudaEventRecord(g_si.evF, 0);
    cudaStreamWaitEvent(g_si.s2, g_si.evF, 0);

    gram2_kernel<<<NC, 256, 0, g_si.s2>>>(C);
    gramstats_kernel<<<1, 256, 0, g_si.s2>>>(out);
    wc2_kernel<<<CCLS, 256, 0, g_si.s2>>>(W, C);
    solve_kernel<<<1, 192, 0, g_si.s2>>>();
    wp2_kernel<<<30, 256, 0, g_si.s2>>>(C);
    pred_kernel<<<Bx / PR, 256, 0, g_si.s2>>>(X, W, b, out);
    cudaEventRecord(g_si.evJ, g_si.s2);

    // main path: score -> topk -> L_sparse_1
    score_mma_kernel<<<(Nn + 255) / 256, 256>>>(C, T);
    topk1_kernel<<<dim3(8, NC), 256>>>();
    topk2_kernel<<<NC, 256>>>();
    finalize_kernel<<<1, 64>>>(out);

    // join
    cudaStreamWaitEvent(0, g_si.evJ, 0);
}